// round 16
// baseline (speedup 1.0000x reference)
#include <cuda_runtime.h>
#include <cstddef>

#define IMH 1024
#define IMW 1024
#define SFRAMES 8
#define NB 4
#define TR 32            // tile rows (output)
#define TC 64            // tile cols
#define NTHREADS 256
#define GH (TR + 8)      // 40 rows incl vertical halo
#define GWF (TC + 8)     // 72: gray tile width incl horizontal halo (floats)
#define NT4 (GH * (GWF / 4))   // 720 float4 gray-load tasks (18 per row)
#define NHT8 (GH * (TC / 8))   // 320 hconv tasks (8 outputs each)

// smem layout (floats): sG[GH*GWF] | sHA[GH*TC] | sHB[GH*TC]
#define SMEM_FLOATS (GH * GWF + 2 * GH * TC)
#define SMEM_BYTES  (SMEM_FLOATS * 4)      // 32,000 B -> 4 CTAs/SM, ~100KB L1D left

__device__ __forceinline__ int reflect101(int i, int n) {
    if (i < 0) i = -i;
    if (i >= n) i = 2 * n - 2 - i;
    return i;
}

// ============================================================================
// Fused: 8-frame laplacian-of-gaussian + argmax + L1-hot winner RGB tracking
//  P1: flat high-MLP gray load -> sG            (R12, proven)
//  P2: hconv, 8 outputs/thread (16-float window, 8 B/px LDS)
//  P3: vertical 9-tap, 4-row x 2-col, 12-row float2 window (R12, proven)
//  smem kept at 32 KB so L1D carveout stays large (winner-reload hits L1).
// ============================================================================
extern "C" __global__ void __launch_bounds__(NTHREADS, 4)
lap_merge_kernel(const float* __restrict__ x, float* __restrict__ out)
{
    extern __shared__ float smem[];
    float* sG  = smem;                      // GH x GWF gray (+halo)
    float* sHA = smem + GH * GWF;           // GH x TC horizontal A-filtered
    float* sHB = sHA + GH * TC;             // GH x TC horizontal B-filtered

    const int tid = threadIdx.x;
    const int b   = blockIdx.z;
    const int hr0 = blockIdx.y * TR;
    const int wc0 = blockIdx.x * TC;
    const size_t HW = (size_t)IMH * IMW;
    const float ONE3 = 0.33333334f;
    const bool interior = (blockIdx.x != 0) && ((int)blockIdx.x != (int)gridDim.x - 1);

    // per-thread state: 8 px = 4 rows x 2 consecutive cols
    const int r0 = (tid >> 5) * 4;          // 8 warps x 4 rows = 32 rows
    const int cg = tid & 31;                // 32 col-groups x 2 = 64 cols

    float bestLap[4][2], bR[4][2], bG[4][2], bB[4][2];
#pragma unroll
    for (int rr = 0; rr < 4; rr++)
#pragma unroll
        for (int o = 0; o < 2; o++) bestLap[rr][o] = -3.0e38f;

    for (int s = 0; s < SFRAMES; s++) {
        const float* __restrict__ xf = x + ((size_t)(b * SFRAMES + s)) * 3 * HW;

        // ==== Phase 1: gray tile load (flat, high-MLP) ====
        if (interior) {
#pragma unroll
            for (int k = 0; k < 3; k++) {
                const int t = tid + k * NTHREADS;
                if (t < NT4) {
                    const int r  = t / (GWF / 4);
                    const int c4 = t - r * (GWF / 4);
                    const int gr = reflect101(hr0 - 4 + r, IMH);
                    const float* __restrict__ p = xf + (size_t)gr * IMW + (wc0 - 4 + c4 * 4);
                    float4 a  = *reinterpret_cast<const float4*>(p);
                    float4 bq = *reinterpret_cast<const float4*>(p + HW);
                    float4 c  = *reinterpret_cast<const float4*>(p + 2 * HW);
                    float4 g;
                    g.x = (a.x + bq.x + c.x) * ONE3;
                    g.y = (a.y + bq.y + c.y) * ONE3;
                    g.z = (a.z + bq.z + c.z) * ONE3;
                    g.w = (a.w + bq.w + c.w) * ONE3;
                    *reinterpret_cast<float4*>(&sG[r * GWF + c4 * 4]) = g;
                }
            }
        } else {
            for (int i = tid; i < GH * GWF; i += NTHREADS) {
                const int r = i / GWF;
                const int c = i - r * GWF;
                const int gr = reflect101(hr0 - 4 + r, IMH);
                const int gc = reflect101(wc0 - 4 + c, IMW);
                const float* __restrict__ p = xf + (size_t)gr * IMW + gc;
                sG[i] = (__ldg(p) + __ldg(p + HW) + __ldg(p + 2 * HW)) * ONE3;
            }
        }
        __syncthreads();

        // ==== Phase 2: horizontal 9-tap A/B, 8 outputs/thread ====
#pragma unroll
        for (int k = 0; k < 2; k++) {
            const int t = tid + k * NTHREADS;
            if (t < NHT8) {
                const int r  = t >> 3;          // 40 rows
                const int c8 = t & 7;           // 8 groups of 8 cols
                float w[16];
#pragma unroll
                for (int j = 0; j < 16; j += 4)
                    *reinterpret_cast<float4*>(&w[j]) =
                        *reinterpret_cast<const float4*>(&sG[r * GWF + c8 * 8 + j]);
                float4 hA4, hB4;
                // first 4 outputs
#pragma unroll
                for (int o = 0; o < 4; o++) {
                    float p1 = w[o + 3] + w[o + 5];
                    float p2 = w[o + 2] + w[o + 6];
                    float p3 = w[o + 1] + w[o + 7];
                    float p4 = w[o + 0] + w[o + 8];
                    float ctr = w[o + 4];
                    (&hA4.x)[o] =  4.375f * ctr + 3.5f  * p1 + 1.75f * p2 + 0.5f  * p3 + 0.0625f * p4;
                    (&hB4.x)[o] = -0.625f * ctr - 0.25f * p1 + 0.25f * p2 + 0.25f * p3 + 0.0625f * p4;
                }
                *reinterpret_cast<float4*>(&sHA[r * TC + c8 * 8])     = hA4;
                *reinterpret_cast<float4*>(&sHB[r * TC + c8 * 8])     = hB4;
                // second 4 outputs
#pragma unroll
                for (int o = 4; o < 8; o++) {
                    float p1 = w[o + 3] + w[o + 5];
                    float p2 = w[o + 2] + w[o + 6];
                    float p3 = w[o + 1] + w[o + 7];
                    float p4 = w[o + 0] + w[o + 8];
                    float ctr = w[o + 4];
                    (&hA4.x)[o - 4] =  4.375f * ctr + 3.5f  * p1 + 1.75f * p2 + 0.5f  * p3 + 0.0625f * p4;
                    (&hB4.x)[o - 4] = -0.625f * ctr - 0.25f * p1 + 0.25f * p2 + 0.25f * p3 + 0.0625f * p4;
                }
                *reinterpret_cast<float4*>(&sHA[r * TC + c8 * 8 + 4]) = hA4;
                *reinterpret_cast<float4*>(&sHB[r * TC + c8 * 8 + 4]) = hB4;
            }
        }
        __syncthreads();

        // ==== Phase 3: vertical 9-tap (B on hA + A on hB), 12-row window + argmax ====
        {
            const float wAv[9] = {0.0625f, 0.5f, 1.75f, 3.5f, 4.375f, 3.5f, 1.75f, 0.5f, 0.0625f};
            const float wBv[9] = {0.0625f, 0.25f, 0.25f, -0.25f, -0.625f, -0.25f, 0.25f, 0.25f, 0.0625f};
            float acc[4][2];
#pragma unroll
            for (int rr = 0; rr < 4; rr++) { acc[rr][0] = 0.f; acc[rr][1] = 0.f; }

#pragma unroll
            for (int j = 0; j < 12; j++) {
                const float2 ha = *reinterpret_cast<const float2*>(&sHA[(r0 + j) * TC + cg * 2]);
                const float2 hb = *reinterpret_cast<const float2*>(&sHB[(r0 + j) * TC + cg * 2]);
#pragma unroll
                for (int rr = 0; rr < 4; rr++) {
                    const int jj = j - rr;
                    if (jj >= 0 && jj <= 8) {     // static after unroll
                        acc[rr][0] += wBv[jj] * ha.x + wAv[jj] * hb.x;
                        acc[rr][1] += wBv[jj] * ha.y + wAv[jj] * hb.y;
                    }
                }
            }
#pragma unroll
            for (int rr = 0; rr < 4; rr++) {
                const size_t pix = (size_t)(hr0 + r0 + rr) * IMW + (wc0 + cg * 2);
#pragma unroll
                for (int o = 0; o < 2; o++) {
                    if (acc[rr][o] > bestLap[rr][o]) {  // strict > == first-max (jnp.argmax)
                        bestLap[rr][o] = acc[rr][o];
                        // winner RGB reload: bytes just read by phase 1 -> L1 hit
                        const float* __restrict__ xw = xf + pix + o;
                        bR[rr][o] = __ldg(xw);
                        bG[rr][o] = __ldg(xw + HW);
                        bB[rr][o] = __ldg(xw + 2 * HW);
                    }
                }
            }
        }
        __syncthreads();   // sG/sHA/sHB reused by next frame
    }

    // ==== Epilogue: write winner RGB (b, c, h, w) as float2 per row/channel ====
#pragma unroll
    for (int rr = 0; rr < 4; rr++) {
        const size_t obase = ((size_t)(b * 3) * IMH + (hr0 + r0 + rr)) * IMW + wc0 + cg * 2;
        *reinterpret_cast<float2*>(out + obase)          = make_float2(bR[rr][0], bR[rr][1]);
        *reinterpret_cast<float2*>(out + obase + HW)     = make_float2(bG[rr][0], bG[rr][1]);
        *reinterpret_cast<float2*>(out + obase + 2 * HW) = make_float2(bB[rr][0], bB[rr][1]);
    }
}

// ============================================================================
extern "C" void kernel_launch(void* const* d_in, const int* in_sizes, int n_in,
                              void* d_out, int out_size)
{
    const float* x = (const float*)d_in[0];
    float* out = (float*)d_out;

    cudaFuncSetAttribute(lap_merge_kernel,
                         cudaFuncAttributeMaxDynamicSharedMemorySize, SMEM_BYTES);

    dim3 grid(IMW / TC, IMH / TR, NB);
    lap_merge_kernel<<<grid, NTHREADS, SMEM_BYTES>>>(x, out);
}

// round 17
// speedup vs baseline: 1.7424x; 1.7424x over previous
#include <cuda_runtime.h>
#include <cstddef>

#define IMH 1024
#define IMW 1024
#define SFRAMES 8
#define NB 4
#define TR 32            // tile rows (output)
#define TC 64            // tile cols
#define NTHREADS 256
#define GH (TR + 8)      // 40 rows incl vertical halo
#define GWF (TC + 8)     // 72: gray tile width incl horizontal halo (floats)
#define NT4 (GH * (GWF / 4))   // 720 float4 gray-load tasks (18 per row)
#define NHT (GH * (TC / 4))    // 640 hconv tasks

// smem layout (floats): sG[GH*GWF] | sHA[GH*TC] | sHB[GH*TC]
#define SMEM_FLOATS (GH * GWF + 2 * GH * TC)
#define SMEM_BYTES  (SMEM_FLOATS * 4)      // 32,000 B -> 4 CTAs/SM, big L1D carveout

__device__ __forceinline__ int reflect101(int i, int n) {
    if (i < 0) i = -i;
    if (i >= n) i = 2 * n - 2 - i;
    return i;
}

// ============================================================================
// Fused: 8-frame laplacian-of-gaussian + argmax + L1-hot winner RGB tracking
//  P1: flat high-MLP gray load -> sG           (R12, proven)
//  P2: hconv 4 outputs/thread, lane-consecutive (R12, proven conflict-free)
//  P3: vertical 9-tap, 8-row x 1-col, 16-row scalar window (16 B/px, no conflicts)
// ============================================================================
extern "C" __global__ void __launch_bounds__(NTHREADS, 4)
lap_merge_kernel(const float* __restrict__ x, float* __restrict__ out)
{
    extern __shared__ float smem[];
    float* sG  = smem;                      // GH x GWF gray (+halo)
    float* sHA = smem + GH * GWF;           // GH x TC horizontal A-filtered
    float* sHB = sHA + GH * TC;             // GH x TC horizontal B-filtered

    const int tid = threadIdx.x;
    const int b   = blockIdx.z;
    const int hr0 = blockIdx.y * TR;
    const int wc0 = blockIdx.x * TC;
    const size_t HW = (size_t)IMH * IMW;
    const float ONE3 = 0.33333334f;
    const bool interior = (blockIdx.x != 0) && ((int)blockIdx.x != (int)gridDim.x - 1);

    // per-thread state: 8 px = 8 rows x 1 col
    const int r0  = (tid >> 6) * 8;         // 4 row-groups x 8 rows = 32 rows
    const int col = tid & 63;               // 64 cols (lane-consecutive)

    float bestLap[8], bR[8], bG[8], bB[8];
#pragma unroll
    for (int rr = 0; rr < 8; rr++) bestLap[rr] = -3.0e38f;

    for (int s = 0; s < SFRAMES; s++) {
        const float* __restrict__ xf = x + ((size_t)(b * SFRAMES + s)) * 3 * HW;

        // ==== Phase 1: gray tile load (flat, high-MLP) ====
        if (interior) {
#pragma unroll
            for (int k = 0; k < 3; k++) {
                const int t = tid + k * NTHREADS;
                if (t < NT4) {
                    const int r  = t / (GWF / 4);
                    const int c4 = t - r * (GWF / 4);
                    const int gr = reflect101(hr0 - 4 + r, IMH);
                    const float* __restrict__ p = xf + (size_t)gr * IMW + (wc0 - 4 + c4 * 4);
                    float4 a  = *reinterpret_cast<const float4*>(p);
                    float4 bq = *reinterpret_cast<const float4*>(p + HW);
                    float4 c  = *reinterpret_cast<const float4*>(p + 2 * HW);
                    float4 g;
                    g.x = (a.x + bq.x + c.x) * ONE3;
                    g.y = (a.y + bq.y + c.y) * ONE3;
                    g.z = (a.z + bq.z + c.z) * ONE3;
                    g.w = (a.w + bq.w + c.w) * ONE3;
                    *reinterpret_cast<float4*>(&sG[r * GWF + c4 * 4]) = g;
                }
            }
        } else {
            for (int i = tid; i < GH * GWF; i += NTHREADS) {
                const int r = i / GWF;
                const int c = i - r * GWF;
                const int gr = reflect101(hr0 - 4 + r, IMH);
                const int gc = reflect101(wc0 - 4 + c, IMW);
                const float* __restrict__ p = xf + (size_t)gr * IMW + gc;
                sG[i] = (__ldg(p) + __ldg(p + HW) + __ldg(p + 2 * HW)) * ONE3;
            }
        }
        __syncthreads();

        // ==== Phase 2: horizontal 9-tap A/B from sG -> sHA/sHB (R12 pattern) ====
#pragma unroll
        for (int k = 0; k < 3; k++) {
            const int t = tid + k * NTHREADS;
            if (t < NHT) {
                const int r  = t / (TC / 4);
                const int c2 = t - r * (TC / 4);
                float w[12];
#pragma unroll
                for (int j = 0; j < 12; j += 4)
                    *reinterpret_cast<float4*>(&w[j]) =
                        *reinterpret_cast<const float4*>(&sG[r * GWF + c2 * 4 + j]);
                float4 hA4, hB4;
#pragma unroll
                for (int o = 0; o < 4; o++) {
                    float p1 = w[o + 3] + w[o + 5];
                    float p2 = w[o + 2] + w[o + 6];
                    float p3 = w[o + 1] + w[o + 7];
                    float p4 = w[o + 0] + w[o + 8];
                    float ctr = w[o + 4];
                    (&hA4.x)[o] =  4.375f * ctr + 3.5f  * p1 + 1.75f * p2 + 0.5f  * p3 + 0.0625f * p4;
                    (&hB4.x)[o] = -0.625f * ctr - 0.25f * p1 + 0.25f * p2 + 0.25f * p3 + 0.0625f * p4;
                }
                *reinterpret_cast<float4*>(&sHA[r * TC + c2 * 4]) = hA4;
                *reinterpret_cast<float4*>(&sHB[r * TC + c2 * 4]) = hB4;
            }
        }
        __syncthreads();

        // ==== Phase 3: vertical 9-tap (B on hA + A on hB), 16-row scalar stream ====
        {
            const float wAv[9] = {0.0625f, 0.5f, 1.75f, 3.5f, 4.375f, 3.5f, 1.75f, 0.5f, 0.0625f};
            const float wBv[9] = {0.0625f, 0.25f, 0.25f, -0.25f, -0.625f, -0.25f, 0.25f, 0.25f, 0.0625f};
            float acc[8];
#pragma unroll
            for (int rr = 0; rr < 8; rr++) acc[rr] = 0.f;

#pragma unroll
            for (int j = 0; j < 16; j++) {
                const float va = sHA[(r0 + j) * TC + col];
                const float vb = sHB[(r0 + j) * TC + col];
#pragma unroll
                for (int rr = 0; rr < 8; rr++) {
                    const int jj = j - rr;
                    if (jj >= 0 && jj <= 8) {    // static after unroll
                        acc[rr] += wBv[jj] * va + wAv[jj] * vb;
                    }
                }
            }
#pragma unroll
            for (int rr = 0; rr < 8; rr++) {
                if (acc[rr] > bestLap[rr]) {     // strict > == first-max (jnp.argmax)
                    bestLap[rr] = acc[rr];
                    // winner RGB reload: bytes just read by P1 -> L1 hit
                    const float* __restrict__ xw =
                        xf + (size_t)(hr0 + r0 + rr) * IMW + (wc0 + col);
                    bR[rr] = __ldg(xw);
                    bG[rr] = __ldg(xw + HW);
                    bB[rr] = __ldg(xw + 2 * HW);
                }
            }
        }
        __syncthreads();   // sG/sHA/sHB reused by next frame
    }

    // ==== Epilogue: write winner RGB (b, c, h, w), lane-consecutive scalar ====
#pragma unroll
    for (int rr = 0; rr < 8; rr++) {
        const size_t obase = ((size_t)(b * 3) * IMH + (hr0 + r0 + rr)) * IMW + wc0 + col;
        out[obase]          = bR[rr];
        out[obase + HW]     = bG[rr];
        out[obase + 2 * HW] = bB[rr];
    }
}

// ============================================================================
extern "C" void kernel_launch(void* const* d_in, const int* in_sizes, int n_in,
                              void* d_out, int out_size)
{
    const float* x = (const float*)d_in[0];
    float* out = (float*)d_out;

    cudaFuncSetAttribute(lap_merge_kernel,
                         cudaFuncAttributeMaxDynamicSharedMemorySize, SMEM_BYTES);

    dim3 grid(IMW / TC, IMH / TR, NB);
    lap_merge_kernel<<<grid, NTHREADS, SMEM_BYTES>>>(x, out);
}